// round 14
// baseline (speedup 1.0000x reference)
#include <cuda_runtime.h>
#include <cuda_fp16.h>
#include <cstdint>

// ---------------------------------------------------------------------------
// NeuralCDE rollout — R13 schedule + smem-prefetched q + merged prep.
//   prep1 (1 launch): all transposes, fp16 converts, counter reset
//   prep2 (1 launch): cv=b2@W1a (+b1t), b2ro=b2@Wro+b_ro
//   launch A (768 indep tiles): W21, W2ro, g, z0h
//   persistent: q2 -> y0 -> 49x chain -> o1 (filler) -> final
//   u ping-pong slabs; y/S interleaved float4; q prefetched to smem per tile.
// ---------------------------------------------------------------------------

static constexpr int BATCH = 8192;
static constexpr int DIN   = 1024;
static constexpr int PATHD = 256;
static constexpr int HID   = 1024;
static constexpr int NSTEP = 50;
static constexpr int NCHAIN = NSTEP - 1;               // 49
static constexpr int TPG   = (BATCH/128) * (HID/128);  // 512
static constexpr int ROWB  = BATCH / 128;              // 64

// persistent slot layout
static constexpr int S_Q   = 0;                        // 512
static constexpr int S_Y0  = S_Q + TPG;                // 512
static constexpr int S_CH  = S_Y0 + TPG;               // 49*512
static constexpr int S_O1  = S_CH + NCHAIN * TPG;      // 512
static constexpr int S_FIN = S_O1 + TPG;               // 512
static constexpr int S_END = S_FIN + TPG;
// counters: 0=q, 1=y0, 2..50=chain 0..48, 51=o1
static constexpr int NCTR  = 52;

// ---------------- device scratch ----------------
__device__ __half x0h_buf[(size_t)BATCH * DIN];
__device__ __half gh_buf [(size_t)BATCH * PATHD];
__device__ __half qh_buf [(size_t)BATCH * HID];
__device__ __half z0h_buf[(size_t)BATCH * HID];
__device__ __half u0_buf [(size_t)BATCH * HID];
__device__ __half u1_buf [(size_t)BATCH * HID];
__device__ __half Sh_buf [(size_t)BATCH * HID];
__device__ float  yS_buf [(size_t)BATCH * HID * 2];   // (y0,y1,S0,S1) per 2 cols
__device__ float  o1_buf [(size_t)BATCH * HID];
__device__ __half WpeT  [(size_t)PATHD * DIN];
__device__ __half WhiT  [(size_t)HID * DIN];
__device__ __half W1aT  [(size_t)HID * HID];
__device__ __half W1bT  [(size_t)HID * PATHD];
__device__ __half WroT  [(size_t)HID * HID];
__device__ __half W2h   [(size_t)HID * HID];
__device__ __half W21T_b[(size_t)HID * HID];
__device__ __half W2roT_b[(size_t)HID * HID];
__device__ float  cvec_b[HID];
__device__ float  b1t_b [HID];
__device__ float  b2ro_b[HID];

__device__ unsigned int g_done[NCTR][ROWB];
__device__ unsigned int g_tile_ctr;

// ---------------- tile configuration ----------------
static constexpr int BM = 128, BN = 128, BK = 32;
static constexpr int STAGES = 3, NTHREADS = 256;
static constexpr int STR  = BK + 8;                    // 40 halves
static constexpr int ASZ  = BM * STR;                  // 5120
static constexpr int BSZ  = BN * STR;                  // 5120
static constexpr int SMEM_PIPE = STAGES * (ASZ + BSZ) * 2;   // 61440 B
static constexpr int QSTR = 136;                       // padded q row (halves)
static constexpr int SMEM_Q = BM * QSTR * 2;           // 34816 B
static constexpr int SMEM_CHAIN = SMEM_PIPE + SMEM_Q;  // 96256 B

__device__ __forceinline__ void ldmx4(uint32_t& r0, uint32_t& r1,
                                      uint32_t& r2, uint32_t& r3, uint32_t a) {
    asm volatile("ldmatrix.sync.aligned.m8n8.x4.shared.b16 {%0,%1,%2,%3}, [%4];"
                 : "=r"(r0), "=r"(r1), "=r"(r2), "=r"(r3) : "r"(a));
}
__device__ __forceinline__ float tanh_ap(float x) {
    float y;
    asm("tanh.approx.f32 %0, %1;" : "=f"(y) : "f"(x));
    return y;
}
__device__ __forceinline__ void spin_ge(volatile unsigned int* c, unsigned int v) {
    while (*c < v) __nanosleep(64);
}

// acc = A[bm*128.., :K] @ B[bn*128.., :K]^T
__device__ __forceinline__ void mainloop_f16(
    const __half* __restrict__ A, const __half* __restrict__ Bw,
    int K, int bm, int bn, __half* As, __half* Bs,
    float (&acc)[4][4][4])
{
    const int tid  = threadIdx.x;
    const int wid  = tid >> 5, lane = tid & 31;
    const int warp_m = wid & 1, warp_n = wid >> 1;
    const int KT = K / BK;

#pragma unroll
    for (int a = 0; a < 4; ++a)
#pragma unroll
        for (int b = 0; b < 4; ++b)
#pragma unroll
            for (int c = 0; c < 4; ++c) acc[a][b][c] = 0.f;

    auto load_tile = [&](int kt, int stage) {
        const __half* Ag = A + (size_t)(bm * BM) * K + (size_t)kt * BK;
        __half* Asb = As + stage * ASZ;
#pragma unroll
        for (int i = 0; i < 2; ++i) {
            int lin = i * NTHREADS + tid;
            int r = lin >> 2, c = (lin & 3) << 3;
            uint32_t sa = (uint32_t)__cvta_generic_to_shared(Asb + r * STR + c);
            asm volatile("cp.async.cg.shared.global [%0], [%1], 16;"
                         :: "r"(sa), "l"(Ag + (size_t)r * K + c));
        }
        const __half* Bg = Bw + (size_t)(bn * BN) * K + (size_t)kt * BK;
        __half* Bsb = Bs + stage * BSZ;
#pragma unroll
        for (int i = 0; i < 2; ++i) {
            int lin = i * NTHREADS + tid;
            int r = lin >> 2, c = (lin & 3) << 3;
            uint32_t sa = (uint32_t)__cvta_generic_to_shared(Bsb + r * STR + c);
            asm volatile("cp.async.cg.shared.global [%0], [%1], 16;"
                         :: "r"(sa), "l"(Bg + (size_t)r * K + c));
        }
        asm volatile("cp.async.commit_group;");
    };

    const int a_row  = warp_m * 64 + (lane & 15);
    const int a_koff = (lane >> 4) << 3;
    const int b_row  = warp_n * 32 + (lane & 7) + ((lane >> 4) << 3);
    const int b_koff = ((lane >> 3) & 1) << 3;

    for (int s = 0; s < STAGES - 1 && s < KT; ++s) load_tile(s, s);

    for (int kt = 0; kt < KT; ++kt) {
        if (kt < KT - (STAGES - 1))
            asm volatile("cp.async.wait_group %0;" :: "n"(STAGES - 2));
        else
            asm volatile("cp.async.wait_group 0;");
        __syncthreads();

        int pf = kt + STAGES - 1;
        if (pf < KT) load_tile(pf, pf % STAGES);

        const __half* Asb = As + (kt % STAGES) * ASZ;
        const __half* Bsb = Bs + (kt % STAGES) * BSZ;
        const uint32_t a_base = (uint32_t)__cvta_generic_to_shared(
            Asb + (size_t)a_row * STR + a_koff);
        const uint32_t b_base = (uint32_t)__cvta_generic_to_shared(
            Bsb + (size_t)b_row * STR + b_koff);

#pragma unroll
        for (int ks = 0; ks < BK / 16; ++ks) {
            uint32_t af[4][4], bf[4][2];
#pragma unroll
            for (int mi = 0; mi < 4; ++mi)
                ldmx4(af[mi][0], af[mi][1], af[mi][2], af[mi][3],
                      a_base + (mi * 16 * STR + ks * 16) * 2);
#pragma unroll
            for (int np = 0; np < 2; ++np)
                ldmx4(bf[np*2][0], bf[np*2][1], bf[np*2+1][0], bf[np*2+1][1],
                      b_base + (np * 16 * STR + ks * 16) * 2);
#pragma unroll
            for (int mi = 0; mi < 4; ++mi)
#pragma unroll
                for (int ni = 0; ni < 4; ++ni) {
                    asm volatile(
                        "mma.sync.aligned.m16n8k16.row.col.f32.f16.f16.f32 "
                        "{%0,%1,%2,%3}, {%4,%5,%6,%7}, {%8,%9}, {%0,%1,%2,%3};"
                        : "+f"(acc[mi][ni][0]), "+f"(acc[mi][ni][1]),
                          "+f"(acc[mi][ni][2]), "+f"(acc[mi][ni][3])
                        : "r"(af[mi][0]), "r"(af[mi][1]), "r"(af[mi][2]), "r"(af[mi][3]),
                          "r"(bf[ni][0]), "r"(bf[ni][1]));
                }
        }
    }
}

// ---------------------------------------------------------------------------
// launch A: merged independent prologue GEMMs (768 one-tile blocks)
// ---------------------------------------------------------------------------
__global__ __launch_bounds__(NTHREADS, 2)
void gemm_indep(const __half* __restrict__ x0h,
                const __half* __restrict__ wpe, const __half* __restrict__ whi,
                const __half* __restrict__ w1a, const __half* __restrict__ wro,
                const __half* __restrict__ w2h,
                __half* __restrict__ w21, __half* __restrict__ w2ro,
                __half* __restrict__ gh, __half* __restrict__ z0h,
                const float* __restrict__ b_pe, const float* __restrict__ b_hi)
{
    extern __shared__ __half smem[];
    __half* As = smem;
    __half* Bs = smem + STAGES * ASZ;

    const int v = blockIdx.x;
    const __half* A;
    const __half* Bw;
    __half* C;
    const float* bias = nullptr;
    int K = HID, N = HID, bm, bn;

    if (v < 64)        { A = w1a; Bw = w2h; C = w21;  bm = v >> 3; bn = v & 7; }
    else if (v < 128)  { A = wro; Bw = w2h; C = w2ro; int t = v - 64; bm = t >> 3; bn = t & 7; }
    else if (v < 256)  { A = x0h; Bw = wpe; C = gh; bias = b_pe; K = DIN; N = PATHD;
                         int t = v - 128; bm = t >> 1; bn = t & 1; }
    else               { A = x0h; Bw = whi; C = z0h; bias = b_hi; K = DIN;
                         int t = v - 256; bm = t >> 3; bn = t & 7; }

    float acc[4][4][4];
    mainloop_f16(A, Bw, K, bm, bn, As, Bs, acc);

    const int tid = threadIdx.x, wid = tid >> 5, lane = tid & 31;
    const int gid = lane >> 2, tig = lane & 3;
    const int rbase = bm * BM + (wid & 1) * 64;
    const int cbase = bn * BN + (wid >> 1) * 32;
#pragma unroll
    for (int mi = 0; mi < 4; ++mi)
#pragma unroll
        for (int h2 = 0; h2 < 2; ++h2) {
            int row = rbase + mi * 16 + h2 * 8 + gid;
#pragma unroll
            for (int ni = 0; ni < 4; ++ni) {
                int col = cbase + ni * 8 + tig * 2;
                size_t off = (size_t)row * N + col;
                float v0 = acc[mi][ni][h2 * 2 + 0];
                float v1 = acc[mi][ni][h2 * 2 + 1];
                if (bias) { v0 += bias[col]; v1 += bias[col + 1]; }
                *reinterpret_cast<__half2*>(C + off) = __floats2half2_rn(v0, v1);
            }
        }
}

// ---------------------------------------------------------------------------
// persistent kernel: q -> y0 -> 49 chain -> o1 -> final, q prefetched to smem
// ---------------------------------------------------------------------------
__global__ __launch_bounds__(NTHREADS, 2)
void cde_chain(const __half* __restrict__ gh, const __half* __restrict__ w1b,
               const __half* __restrict__ w1a,
               const __half* __restrict__ W21, const __half* __restrict__ wro,
               const __half* __restrict__ w2ro,
               const __half* __restrict__ z0h,
               __half* __restrict__ u0s, __half* __restrict__ u1s,
               __half* __restrict__ Sh, __half* __restrict__ qh,
               float* __restrict__ yS,
               float* __restrict__ o1, float* __restrict__ out,
               const float* __restrict__ cv,
               const float* __restrict__ b1t, const float* __restrict__ b2ro,
               float dt)
{
    extern __shared__ __half smem[];
    __half* As = smem;
    __half* Bs = smem + STAGES * ASZ;
    __half* Qs = smem + STAGES * (ASZ + BSZ);
    __shared__ unsigned int s_tile;

    const int tid = threadIdx.x, wid = tid >> 5, lane = tid & 31;
    const int gid = lane >> 2, tig = lane & 3;

    while (true) {
        if (tid == 0) s_tile = atomicAdd(&g_tile_ctr, 1u);
        __syncthreads();
        unsigned int v = s_tile;
        if (v >= (unsigned)S_END) break;

        // kind: 0=q 1=y0 2=chain 3=o1 4=final
        int kind, gidx = 0, t;
        if (v < (unsigned)S_Y0)       { kind = 0; t = v; }
        else if (v < (unsigned)S_CH)  { kind = 1; t = v - S_Y0; }
        else if (v < (unsigned)S_O1)  { kind = 2; gidx = (v - S_CH) >> 9; t = (v - S_CH) & 511; }
        else if (v < (unsigned)S_FIN) { kind = 3; t = v - S_O1; }
        else                          { kind = 4; t = v - S_FIN; }
        const int bm = t >> 3, bn = t & 7;

        // dependencies (row-block granularity; strictly earlier slots only)
        if (tid == 0) {
            if (kind == 1) {
                spin_ge(&g_done[0][bm], 8u);
                __threadfence();
            } else if (kind == 2) {
                spin_ge(&g_done[1 + gidx][bm], 8u);
                __threadfence();
            } else if (kind == 4) {
                spin_ge(&g_done[1 + NCHAIN][bm], 8u);
                spin_ge(&g_done[51][bm], 8u);
                __threadfence();
            }
        }
        __syncthreads();

        // prefetch q tile into smem (first cp.async group; completes before
        // the mainloop's final wait_group 0)
        if (kind == 1 || kind == 2) {
            const __half* Qg = qh + (size_t)(bm * BM) * HID + bn * BN;
#pragma unroll
            for (int i = 0; i < 8; ++i) {
                int lin = i * NTHREADS + tid;
                int r = lin >> 4, c = (lin & 15) << 3;
                uint32_t sa = (uint32_t)__cvta_generic_to_shared(Qs + r * QSTR + c);
                asm volatile("cp.async.cg.shared.global [%0], [%1], 16;"
                             :: "r"(sa), "l"(Qg + (size_t)r * HID + c));
            }
            asm volatile("cp.async.commit_group;");
        }

        const __half* A;
        const __half* Bw;
        int K = HID;
        if (kind == 0)      { A = gh;  Bw = w1b; K = PATHD; }
        else if (kind == 1) { A = z0h; Bw = w1a; }
        else if (kind == 2) { A = ((gidx + 1) & 1) ? u1s : u0s; Bw = W21; }
        else if (kind == 3) { A = z0h; Bw = wro; }
        else                { A = Sh;  Bw = w2ro; }

        float acc[4][4][4];
        mainloop_f16(A, Bw, K, bm, bn, As, Bs, acc);

        const int rbase = bm * BM + (wid & 1) * 64;
        const int cbase = bn * BN + (wid >> 1) * 32;
        const int rloc0 = (wid & 1) * 64;
        const int cloc0 = (wid >> 1) * 32;

        if (kind == 0) {
#pragma unroll
            for (int mi = 0; mi < 4; ++mi)
#pragma unroll
                for (int h2 = 0; h2 < 2; ++h2) {
                    int row = rbase + mi * 16 + h2 * 8 + gid;
#pragma unroll
                    for (int ni = 0; ni < 4; ++ni) {
                        int col = cbase + ni * 8 + tig * 2;
                        size_t off = (size_t)row * HID + col;
                        *reinterpret_cast<__half2*>(qh + off) = __floats2half2_rn(
                            acc[mi][ni][h2 * 2 + 0] + cv[col],
                            acc[mi][ni][h2 * 2 + 1] + cv[col + 1]);
                    }
                }
        } else if (kind == 1) {
#pragma unroll
            for (int mi = 0; mi < 4; ++mi)
#pragma unroll
                for (int h2 = 0; h2 < 2; ++h2) {
                    int row  = rbase + mi * 16 + h2 * 8 + gid;
                    int rloc = rloc0 + mi * 16 + h2 * 8 + gid;
#pragma unroll
                    for (int ni = 0; ni < 4; ++ni) {
                        int col  = cbase + ni * 8 + tig * 2;
                        int cloc = cloc0 + ni * 8 + tig * 2;
                        size_t uoff  = (size_t)row * HID + col;
                        size_t ysoff = (size_t)row * (2 * HID) + col * 2;
                        float a0 = acc[mi][ni][h2 * 2 + 0];
                        float a1 = acc[mi][ni][h2 * 2 + 1];
                        float2 qe = __half22float2(
                            *reinterpret_cast<const __half2*>(Qs + rloc * QSTR + cloc));
                        float u0 = tanh_ap(a0 + dt * qe.x + b1t[col]);
                        float u1 = tanh_ap(a1 + dt * qe.y + b1t[col + 1]);
                        *reinterpret_cast<__half2*>(u1s + uoff) =
                            __floats2half2_rn(u0, u1);
                        *reinterpret_cast<float4*>(yS + ysoff) =
                            make_float4(a0, a1, u0, u1);
                    }
                }
        } else if (kind == 2) {
            __half* Cu = (gidx & 1) ? u1s : u0s;
            const float tcoef = dt * (float)(gidx + 2);
            const bool last = (gidx == NCHAIN - 1);
#pragma unroll
            for (int mi = 0; mi < 4; ++mi)
#pragma unroll
                for (int h2 = 0; h2 < 2; ++h2) {
                    int row  = rbase + mi * 16 + h2 * 8 + gid;
                    int rloc = rloc0 + mi * 16 + h2 * 8 + gid;
#pragma unroll
                    for (int ni = 0; ni < 4; ++ni) {
                        int col  = cbase + ni * 8 + tig * 2;
                        int cloc = cloc0 + ni * 8 + tig * 2;
                        size_t uoff  = (size_t)row * HID + col;
                        size_t ysoff = (size_t)row * (2 * HID) + col * 2;
                        float a0 = acc[mi][ni][h2 * 2 + 0];
                        float a1 = acc[mi][ni][h2 * 2 + 1];
                        float4 ys = __ldcg(reinterpret_cast<const float4*>(yS + ysoff));
                        ys.x += dt * a0;
                        ys.y += dt * a1;
                        float2 qe = __half22float2(
                            *reinterpret_cast<const __half2*>(Qs + rloc * QSTR + cloc));
                        float u0 = tanh_ap(ys.x + tcoef * qe.x + b1t[col]);
                        float u1 = tanh_ap(ys.y + tcoef * qe.y + b1t[col + 1]);
                        ys.z += u0;
                        ys.w += u1;
                        *reinterpret_cast<__half2*>(Cu + uoff) =
                            __floats2half2_rn(u0, u1);
                        *reinterpret_cast<float4*>(yS + ysoff) = ys;
                        if (last)
                            *reinterpret_cast<__half2*>(Sh + uoff) =
                                __floats2half2_rn(ys.z, ys.w);
                    }
                }
        } else if (kind == 3) {
#pragma unroll
            for (int mi = 0; mi < 4; ++mi)
#pragma unroll
                for (int h2 = 0; h2 < 2; ++h2) {
                    int row = rbase + mi * 16 + h2 * 8 + gid;
#pragma unroll
                    for (int ni = 0; ni < 4; ++ni) {
                        int col = cbase + ni * 8 + tig * 2;
                        size_t off = (size_t)row * HID + col;
                        *reinterpret_cast<float2*>(o1 + off) = make_float2(
                            acc[mi][ni][h2 * 2 + 0], acc[mi][ni][h2 * 2 + 1]);
                    }
                }
        } else {
#pragma unroll
            for (int mi = 0; mi < 4; ++mi)
#pragma unroll
                for (int h2 = 0; h2 < 2; ++h2) {
                    int row = rbase + mi * 16 + h2 * 8 + gid;
#pragma unroll
                    for (int ni = 0; ni < 4; ++ni) {
                        int col = cbase + ni * 8 + tig * 2;
                        size_t off = (size_t)row * HID + col;
                        float2 ov = __ldcg(reinterpret_cast<const float2*>(o1 + off));
                        *reinterpret_cast<float2*>(out + off) = make_float2(
                            ov.x + dt * acc[mi][ni][h2 * 2 + 0] + b2ro[col],
                            ov.y + dt * acc[mi][ni][h2 * 2 + 1] + b2ro[col + 1]);
                    }
                }
        }

        if (kind != 4) {
            __threadfence();
            __syncthreads();
            if (tid == 0) {
                int ci;
                if (kind == 0)      ci = 0;
                else if (kind == 1) ci = 1;
                else if (kind == 2) ci = 2 + gidx;
                else                ci = 51;
                atomicAdd(&g_done[ci][bm], 1u);
            }
        }
    }
}

// ---------------------------------------------------------------------------
// prep1: all transposes + fp16 conversions + counter reset, one launch
// ---------------------------------------------------------------------------
__device__ __forceinline__ void transpose_block(
    const float* __restrict__ in, __half* __restrict__ out,
    int K, int N, int bx, int by, int tid)
{
    __shared__ float t[32][33];
    const int k0 = by * 32, n0 = bx * 32;
    const int x = tid & 31, y = tid >> 5;   // y in 0..7
#pragma unroll
    for (int i = 0; i < 32; i += 8)
        t[y + i][x] = in[(size_t)(k0 + y + i) * N + n0 + x];
    __syncthreads();
#pragma unroll
    for (int i = 0; i < 32; i += 8)
        out[(size_t)(n0 + y + i) * K + k0 + x] = __float2half_rn(t[x][y + i]);
}

__global__ void prep1(const float* __restrict__ x0,
                      const float* __restrict__ W_pe, const float* __restrict__ W_hi,
                      const float* __restrict__ W1,  const float* __restrict__ W_ro,
                      const float* __restrict__ W2,
                      __half* __restrict__ wpe, __half* __restrict__ whi,
                      __half* __restrict__ w1a, __half* __restrict__ w1b,
                      __half* __restrict__ wro,
                      __half* __restrict__ x0h, __half* __restrict__ w2h)
{
    const int b = blockIdx.x, tid = threadIdx.x;
    // [0,256): Wpe  (8 x 32)    [256,1280): Whi (32 x 32)
    // [1280,2304): W1a          [2304,2560): W1b (32 x 8)
    // [2560,3584): Wro
    // [3584,11776): x0 -> fp16  [11776,12800): W2 -> fp16
    // [12800,12814): zero counters
    if (b < 256) {
        transpose_block(W_pe, wpe, DIN, PATHD, b & 7, b >> 3, tid);
    } else if (b < 1280) {
        int v = b - 256;  transpose_block(W_hi, whi, DIN, HID, v & 31, v >> 5, tid);
    } else if (b < 2304) {
        int v = b - 1280; transpose_block(W1, w1a, HID, HID, v & 31, v >> 5, tid);
    } else if (b < 2560) {
        int v = b - 2304; transpose_block(W1 + (size_t)HID * HID, w1b,
                                          PATHD, HID, v & 31, v >> 5, tid);
    } else if (b < 3584) {
        int v = b - 2560; transpose_block(W_ro, wro, HID, HID, v & 31, v >> 5, tid);
    } else if (b < 11776) {
        int i = (b - 3584) * 256 + tid;           // n4 = 2097152
        float4 v = reinterpret_cast<const float4*>(x0)[i];
        __half2* o = reinterpret_cast<__half2*>(x0h);
        o[i * 2 + 0] = __floats2half2_rn(v.x, v.y);
        o[i * 2 + 1] = __floats2half2_rn(v.z, v.w);
    } else if (b < 12800) {
        int i = (b - 11776) * 256 + tid;          // w4 = 262144
        float4 v = reinterpret_cast<const float4*>(W2)[i];
        __half2* o = reinterpret_cast<__half2*>(w2h);
        o[i * 2 + 0] = __floats2half2_rn(v.x, v.y);
        o[i * 2 + 1] = __floats2half2_rn(v.z, v.w);
    } else {
        int i = (b - 12800) * 256 + tid;
        int n = NCTR * ROWB;
        unsigned int* p = &g_done[0][0];
        if (i < n) p[i] = 0;
        if (i == n) g_tile_ctr = 0;
    }
}

// ---------------------------------------------------------------------------
// prep2: cv = b2@W1a (+ b1t), b2ro = b2@Wro + b_ro
// ---------------------------------------------------------------------------
__global__ void prep2(const __half* __restrict__ w1a, const __half* __restrict__ wro,
                      const float* __restrict__ b1, const float* __restrict__ b2,
                      const float* __restrict__ b_ro,
                      float* __restrict__ cv, float* __restrict__ b1t,
                      float* __restrict__ b2ro, float dt)
{
    __shared__ float red[256];
    const int b = blockIdx.x;
    const bool first = (b < HID);
    const int n = first ? b : (b - HID);
    const __half* Wt = first ? w1a : wro;
    float s = 0.f;
    for (int j = threadIdx.x; j < HID; j += 256)
        s += b2[j] * __half2float(Wt[(size_t)n * HID + j]);
    red[threadIdx.x] = s;
    __syncthreads();
    for (int k = 128; k > 0; k >>= 1) {
        if (threadIdx.x < k) red[threadIdx.x] += red[threadIdx.x + k];
        __syncthreads();
    }
    if (threadIdx.x == 0) {
        if (first) { cv[n] = red[0]; b1t[n] = b1[n] - dt * red[0]; }
        else       { b2ro[n] = red[0] + b_ro[n]; }
    }
}

extern "C" void kernel_launch(void* const* d_in, const int* in_sizes, int n_in,
                              void* d_out, int out_size)
{
    const float* x0   = (const float*)d_in[0];
    const float* W_pe = (const float*)d_in[1];
    const float* b_pe = (const float*)d_in[2];
    const float* W_hi = (const float*)d_in[3];
    const float* b_hi = (const float*)d_in[4];
    const float* W1   = (const float*)d_in[5];
    const float* b1   = (const float*)d_in[6];
    const float* W2   = (const float*)d_in[7];
    const float* b2   = (const float*)d_in[8];
    const float* W_ro = (const float*)d_in[9];
    const float* b_ro = (const float*)d_in[10];
    float* out = (float*)d_out;

    __half *x0h, *gh, *qh, *z0h, *u0s, *u1s, *Shp;
    __half *wpe, *whi, *w1a, *w1b, *wro, *w2h, *w21, *w2ro;
    float *yS, *o1, *cv, *b1t, *b2ro;
    cudaGetSymbolAddress((void**)&x0h, x0h_buf);
    cudaGetSymbolAddress((void**)&gh,  gh_buf);
    cudaGetSymbolAddress((void**)&qh,  qh_buf);
    cudaGetSymbolAddress((void**)&z0h, z0h_buf);
    cudaGetSymbolAddress((void**)&u0s, u0_buf);
    cudaGetSymbolAddress((void**)&u1s, u1_buf);
    cudaGetSymbolAddress((void**)&Shp, Sh_buf);
    cudaGetSymbolAddress((void**)&yS,  yS_buf);
    cudaGetSymbolAddress((void**)&o1,  o1_buf);
    cudaGetSymbolAddress((void**)&wpe, WpeT);
    cudaGetSymbolAddress((void**)&whi, WhiT);
    cudaGetSymbolAddress((void**)&w1a, W1aT);
    cudaGetSymbolAddress((void**)&w1b, W1bT);
    cudaGetSymbolAddress((void**)&wro, WroT);
    cudaGetSymbolAddress((void**)&w2h, W2h);
    cudaGetSymbolAddress((void**)&w21, W21T_b);
    cudaGetSymbolAddress((void**)&w2ro, W2roT_b);
    cudaGetSymbolAddress((void**)&cv,  cvec_b);
    cudaGetSymbolAddress((void**)&b1t, b1t_b);
    cudaGetSymbolAddress((void**)&b2ro, b2ro_b);

    const float dt = 1.0f / (float)NSTEP;

    // prep1: transposes + conversions + counter reset (one launch)
    prep1<<<12814, 256>>>(x0, W_pe, W_hi, W1, W_ro, W2,
                          wpe, whi, w1a, w1b, wro, x0h, w2h);

    // prep2: cv/b1t/b2ro (one launch)
    prep2<<<2 * HID, 256>>>(w1a, wro, b1, b2, b_ro, cv, b1t, b2ro, dt);

    // launch A: all independent GEMMs in one grid
    cudaFuncSetAttribute(gemm_indep,
                         cudaFuncAttributeMaxDynamicSharedMemorySize, SMEM_PIPE);
    gemm_indep<<<768, NTHREADS, SMEM_PIPE>>>(
        x0h, wpe, whi, w1a, wro, w2h, w21, w2ro, gh, z0h, b_pe, b_hi);

    // persistent: q -> y0 -> chain -> o1 -> final
    int dev = 0, nsm = 148;
    cudaGetDevice(&dev);
    cudaDeviceGetAttribute(&nsm, cudaDevAttrMultiProcessorCount, dev);
    cudaFuncSetAttribute(cde_chain,
                         cudaFuncAttributeMaxDynamicSharedMemorySize, SMEM_CHAIN);
    cde_chain<<<2 * nsm, NTHREADS, SMEM_CHAIN>>>(
        gh, w1b, w1a, w21, wro, w2ro, z0h, u0s, u1s, Shp, qh,
        yS, o1, out, cv, b1t, b2ro, dt);
}

// round 15
// speedup vs baseline: 1.0084x; 1.0084x over previous
#include <cuda_runtime.h>
#include <cuda_fp16.h>
#include <cstdint>

// ---------------------------------------------------------------------------
// NeuralCDE rollout — R13 schedule (4-stage pipeline) + merged prep launches.
//   prep1 (1 launch): all transposes, fp16 converts, counter reset
//   prep2 (1 launch): cv=b2@W1a (+b1t), b2ro=b2@Wro+b_ro
//   launch A (768 indep tiles): W21, W2ro, g, z0h
//   persistent: q2 -> y0 -> 49x chain -> o1 (filler) -> final
//   u ping-pong slabs; y/S interleaved float4 stream.
// ---------------------------------------------------------------------------

static constexpr int BATCH = 8192;
static constexpr int DIN   = 1024;
static constexpr int PATHD = 256;
static constexpr int HID   = 1024;
static constexpr int NSTEP = 50;
static constexpr int NCHAIN = NSTEP - 1;               // 49
static constexpr int TPG   = (BATCH/128) * (HID/128);  // 512
static constexpr int ROWB  = BATCH / 128;              // 64

// persistent slot layout
static constexpr int S_Q   = 0;                        // 512
static constexpr int S_Y0  = S_Q + TPG;                // 512
static constexpr int S_CH  = S_Y0 + TPG;               // 49*512
static constexpr int S_O1  = S_CH + NCHAIN * TPG;      // 512
static constexpr int S_FIN = S_O1 + TPG;               // 512
static constexpr int S_END = S_FIN + TPG;
// counters: 0=q, 1=y0, 2..50=chain 0..48, 51=o1
static constexpr int NCTR  = 52;

// ---------------- device scratch ----------------
__device__ __half x0h_buf[(size_t)BATCH * DIN];
__device__ __half gh_buf [(size_t)BATCH * PATHD];
__device__ __half qh_buf [(size_t)BATCH * HID];
__device__ __half z0h_buf[(size_t)BATCH * HID];
__device__ __half u0_buf [(size_t)BATCH * HID];
__device__ __half u1_buf [(size_t)BATCH * HID];
__device__ __half Sh_buf [(size_t)BATCH * HID];
__device__ float  yS_buf [(size_t)BATCH * HID * 2];   // (y0,y1,S0,S1) per 2 cols
__device__ float  o1_buf [(size_t)BATCH * HID];
__device__ __half WpeT  [(size_t)PATHD * DIN];
__device__ __half WhiT  [(size_t)HID * DIN];
__device__ __half W1aT  [(size_t)HID * HID];
__device__ __half W1bT  [(size_t)HID * PATHD];
__device__ __half WroT  [(size_t)HID * HID];
__device__ __half W2h   [(size_t)HID * HID];
__device__ __half W21T_b[(size_t)HID * HID];
__device__ __half W2roT_b[(size_t)HID * HID];
__device__ float  cvec_b[HID];
__device__ float  b1t_b [HID];
__device__ float  b2ro_b[HID];

__device__ unsigned int g_done[NCTR][ROWB];
__device__ unsigned int g_tile_ctr;

// ---------------- tile configuration ----------------
static constexpr int BM = 128, BN = 128, BK = 32;
static constexpr int STAGES = 4, NTHREADS = 256;
static constexpr int STR  = BK + 8;                    // 40 halves
static constexpr int ASZ  = BM * STR;                  // 5120
static constexpr int BSZ  = BN * STR;                  // 5120
static constexpr int SMEM_BYTES = STAGES * (ASZ + BSZ) * 2;  // 81920

__device__ __forceinline__ void ldmx4(uint32_t& r0, uint32_t& r1,
                                      uint32_t& r2, uint32_t& r3, uint32_t a) {
    asm volatile("ldmatrix.sync.aligned.m8n8.x4.shared.b16 {%0,%1,%2,%3}, [%4];"
                 : "=r"(r0), "=r"(r1), "=r"(r2), "=r"(r3) : "r"(a));
}
__device__ __forceinline__ float tanh_ap(float x) {
    float y;
    asm("tanh.approx.f32 %0, %1;" : "=f"(y) : "f"(x));
    return y;
}
__device__ __forceinline__ void spin_ge(volatile unsigned int* c, unsigned int v) {
    while (*c < v) __nanosleep(64);
}

// acc = A[bm*128.., :K] @ B[bn*128.., :K]^T
__device__ __forceinline__ void mainloop_f16(
    const __half* __restrict__ A, const __half* __restrict__ Bw,
    int K, int bm, int bn, __half* As, __half* Bs,
    float (&acc)[4][4][4])
{
    const int tid  = threadIdx.x;
    const int wid  = tid >> 5, lane = tid & 31;
    const int warp_m = wid & 1, warp_n = wid >> 1;
    const int KT = K / BK;

#pragma unroll
    for (int a = 0; a < 4; ++a)
#pragma unroll
        for (int b = 0; b < 4; ++b)
#pragma unroll
            for (int c = 0; c < 4; ++c) acc[a][b][c] = 0.f;

    auto load_tile = [&](int kt, int stage) {
        const __half* Ag = A + (size_t)(bm * BM) * K + (size_t)kt * BK;
        __half* Asb = As + stage * ASZ;
#pragma unroll
        for (int i = 0; i < 2; ++i) {
            int lin = i * NTHREADS + tid;
            int r = lin >> 2, c = (lin & 3) << 3;
            uint32_t sa = (uint32_t)__cvta_generic_to_shared(Asb + r * STR + c);
            asm volatile("cp.async.cg.shared.global [%0], [%1], 16;"
                         :: "r"(sa), "l"(Ag + (size_t)r * K + c));
        }
        const __half* Bg = Bw + (size_t)(bn * BN) * K + (size_t)kt * BK;
        __half* Bsb = Bs + stage * BSZ;
#pragma unroll
        for (int i = 0; i < 2; ++i) {
            int lin = i * NTHREADS + tid;
            int r = lin >> 2, c = (lin & 3) << 3;
            uint32_t sa = (uint32_t)__cvta_generic_to_shared(Bsb + r * STR + c);
            asm volatile("cp.async.cg.shared.global [%0], [%1], 16;"
                         :: "r"(sa), "l"(Bg + (size_t)r * K + c));
        }
        asm volatile("cp.async.commit_group;");
    };

    const int a_row  = warp_m * 64 + (lane & 15);
    const int a_koff = (lane >> 4) << 3;
    const int b_row  = warp_n * 32 + (lane & 7) + ((lane >> 4) << 3);
    const int b_koff = ((lane >> 3) & 1) << 3;

    for (int s = 0; s < STAGES - 1 && s < KT; ++s) load_tile(s, s);

    for (int kt = 0; kt < KT; ++kt) {
        if (kt < KT - (STAGES - 1))
            asm volatile("cp.async.wait_group %0;" :: "n"(STAGES - 2));
        else
            asm volatile("cp.async.wait_group 0;");
        __syncthreads();

        int pf = kt + STAGES - 1;
        if (pf < KT) load_tile(pf, pf % STAGES);

        const __half* Asb = As + (kt % STAGES) * ASZ;
        const __half* Bsb = Bs + (kt % STAGES) * BSZ;
        const uint32_t a_base = (uint32_t)__cvta_generic_to_shared(
            Asb + (size_t)a_row * STR + a_koff);
        const uint32_t b_base = (uint32_t)__cvta_generic_to_shared(
            Bsb + (size_t)b_row * STR + b_koff);

#pragma unroll
        for (int ks = 0; ks < BK / 16; ++ks) {
            uint32_t af[4][4], bf[4][2];
#pragma unroll
            for (int mi = 0; mi < 4; ++mi)
                ldmx4(af[mi][0], af[mi][1], af[mi][2], af[mi][3],
                      a_base + (mi * 16 * STR + ks * 16) * 2);
#pragma unroll
            for (int np = 0; np < 2; ++np)
                ldmx4(bf[np*2][0], bf[np*2][1], bf[np*2+1][0], bf[np*2+1][1],
                      b_base + (np * 16 * STR + ks * 16) * 2);
#pragma unroll
            for (int mi = 0; mi < 4; ++mi)
#pragma unroll
                for (int ni = 0; ni < 4; ++ni) {
                    asm volatile(
                        "mma.sync.aligned.m16n8k16.row.col.f32.f16.f16.f32 "
                        "{%0,%1,%2,%3}, {%4,%5,%6,%7}, {%8,%9}, {%0,%1,%2,%3};"
                        : "+f"(acc[mi][ni][0]), "+f"(acc[mi][ni][1]),
                          "+f"(acc[mi][ni][2]), "+f"(acc[mi][ni][3])
                        : "r"(af[mi][0]), "r"(af[mi][1]), "r"(af[mi][2]), "r"(af[mi][3]),
                          "r"(bf[ni][0]), "r"(bf[ni][1]));
                }
        }
    }
}

// ---------------------------------------------------------------------------
// launch A: merged independent prologue GEMMs (768 one-tile blocks)
// ---------------------------------------------------------------------------
__global__ __launch_bounds__(NTHREADS, 2)
void gemm_indep(const __half* __restrict__ x0h,
                const __half* __restrict__ wpe, const __half* __restrict__ whi,
                const __half* __restrict__ w1a, const __half* __restrict__ wro,
                const __half* __restrict__ w2h,
                __half* __restrict__ w21, __half* __restrict__ w2ro,
                __half* __restrict__ gh, __half* __restrict__ z0h,
                const float* __restrict__ b_pe, const float* __restrict__ b_hi)
{
    extern __shared__ __half smem[];
    __half* As = smem;
    __half* Bs = smem + STAGES * ASZ;

    const int v = blockIdx.x;
    const __half* A;
    const __half* Bw;
    __half* C;
    const float* bias = nullptr;
    int K = HID, N = HID, bm, bn;

    if (v < 64)        { A = w1a; Bw = w2h; C = w21;  bm = v >> 3; bn = v & 7; }
    else if (v < 128)  { A = wro; Bw = w2h; C = w2ro; int t = v - 64; bm = t >> 3; bn = t & 7; }
    else if (v < 256)  { A = x0h; Bw = wpe; C = gh; bias = b_pe; K = DIN; N = PATHD;
                         int t = v - 128; bm = t >> 1; bn = t & 1; }
    else               { A = x0h; Bw = whi; C = z0h; bias = b_hi; K = DIN;
                         int t = v - 256; bm = t >> 3; bn = t & 7; }

    float acc[4][4][4];
    mainloop_f16(A, Bw, K, bm, bn, As, Bs, acc);

    const int tid = threadIdx.x, wid = tid >> 5, lane = tid & 31;
    const int gid = lane >> 2, tig = lane & 3;
    const int rbase = bm * BM + (wid & 1) * 64;
    const int cbase = bn * BN + (wid >> 1) * 32;
#pragma unroll
    for (int mi = 0; mi < 4; ++mi)
#pragma unroll
        for (int h2 = 0; h2 < 2; ++h2) {
            int row = rbase + mi * 16 + h2 * 8 + gid;
#pragma unroll
            for (int ni = 0; ni < 4; ++ni) {
                int col = cbase + ni * 8 + tig * 2;
                size_t off = (size_t)row * N + col;
                float v0 = acc[mi][ni][h2 * 2 + 0];
                float v1 = acc[mi][ni][h2 * 2 + 1];
                if (bias) { v0 += bias[col]; v1 += bias[col + 1]; }
                *reinterpret_cast<__half2*>(C + off) = __floats2half2_rn(v0, v1);
            }
        }
}

// ---------------------------------------------------------------------------
// persistent kernel: q -> y0 -> 49 chain -> o1 -> final
// ---------------------------------------------------------------------------
__global__ __launch_bounds__(NTHREADS, 2)
void cde_chain(const __half* __restrict__ gh, const __half* __restrict__ w1b,
               const __half* __restrict__ w1a,
               const __half* __restrict__ W21, const __half* __restrict__ wro,
               const __half* __restrict__ w2ro,
               const __half* __restrict__ z0h,
               __half* __restrict__ u0s, __half* __restrict__ u1s,
               __half* __restrict__ Sh, __half* __restrict__ qh,
               float* __restrict__ yS,
               float* __restrict__ o1, float* __restrict__ out,
               const float* __restrict__ cv,
               const float* __restrict__ b1t, const float* __restrict__ b2ro,
               float dt)
{
    extern __shared__ __half smem[];
    __half* As = smem;
    __half* Bs = smem + STAGES * ASZ;
    __shared__ unsigned int s_tile;

    const int tid = threadIdx.x, wid = tid >> 5, lane = tid & 31;
    const int gid = lane >> 2, tig = lane & 3;

    while (true) {
        if (tid == 0) s_tile = atomicAdd(&g_tile_ctr, 1u);
        __syncthreads();
        unsigned int v = s_tile;
        if (v >= (unsigned)S_END) break;

        // kind: 0=q 1=y0 2=chain 3=o1 4=final
        int kind, gidx = 0, t;
        if (v < (unsigned)S_Y0)       { kind = 0; t = v; }
        else if (v < (unsigned)S_CH)  { kind = 1; t = v - S_Y0; }
        else if (v < (unsigned)S_O1)  { kind = 2; gidx = (v - S_CH) >> 9; t = (v - S_CH) & 511; }
        else if (v < (unsigned)S_FIN) { kind = 3; t = v - S_O1; }
        else                          { kind = 4; t = v - S_FIN; }
        const int bm = t >> 3, bn = t & 7;

        // dependencies (row-block granularity; strictly earlier slots only)
        if (tid == 0) {
            if (kind == 1) {
                spin_ge(&g_done[0][bm], 8u);
                __threadfence();
            } else if (kind == 2) {
                spin_ge(&g_done[1 + gidx][bm], 8u);
                __threadfence();
            } else if (kind == 4) {
                spin_ge(&g_done[1 + NCHAIN][bm], 8u);
                spin_ge(&g_done[51][bm], 8u);
                __threadfence();
            }
        }
        __syncthreads();

        const __half* A;
        const __half* Bw;
        int K = HID;
        if (kind == 0)      { A = gh;  Bw = w1b; K = PATHD; }
        else if (kind == 1) { A = z0h; Bw = w1a; }
        else if (kind == 2) { A = ((gidx + 1) & 1) ? u1s : u0s; Bw = W21; }
        else if (kind == 3) { A = z0h; Bw = wro; }
        else                { A = Sh;  Bw = w2ro; }

        float acc[4][4][4];
        mainloop_f16(A, Bw, K, bm, bn, As, Bs, acc);

        const int rbase = bm * BM + (wid & 1) * 64;
        const int cbase = bn * BN + (wid >> 1) * 32;

        if (kind == 0) {
#pragma unroll
            for (int mi = 0; mi < 4; ++mi)
#pragma unroll
                for (int h2 = 0; h2 < 2; ++h2) {
                    int row = rbase + mi * 16 + h2 * 8 + gid;
#pragma unroll
                    for (int ni = 0; ni < 4; ++ni) {
                        int col = cbase + ni * 8 + tig * 2;
                        size_t off = (size_t)row * HID + col;
                        *reinterpret_cast<__half2*>(qh + off) = __floats2half2_rn(
                            acc[mi][ni][h2 * 2 + 0] + cv[col],
                            acc[mi][ni][h2 * 2 + 1] + cv[col + 1]);
                    }
                }
        } else if (kind == 1) {
#pragma unroll
            for (int mi = 0; mi < 4; ++mi)
#pragma unroll
                for (int h2 = 0; h2 < 2; ++h2) {
                    int row = rbase + mi * 16 + h2 * 8 + gid;
#pragma unroll
                    for (int ni = 0; ni < 4; ++ni) {
                        int col = cbase + ni * 8 + tig * 2;
                        size_t uoff  = (size_t)row * HID + col;
                        size_t ysoff = (size_t)row * (2 * HID) + col * 2;
                        float a0 = acc[mi][ni][h2 * 2 + 0];
                        float a1 = acc[mi][ni][h2 * 2 + 1];
                        float2 qe = __half22float2(
                            *reinterpret_cast<const __half2*>(qh + uoff));
                        float u0 = tanh_ap(a0 + dt * qe.x + b1t[col]);
                        float u1 = tanh_ap(a1 + dt * qe.y + b1t[col + 1]);
                        *reinterpret_cast<__half2*>(u1s + uoff) =
                            __floats2half2_rn(u0, u1);
                        *reinterpret_cast<float4*>(yS + ysoff) =
                            make_float4(a0, a1, u0, u1);
                    }
                }
        } else if (kind == 2) {
            __half* Cu = (gidx & 1) ? u1s : u0s;
            const float tcoef = dt * (float)(gidx + 2);
            const bool last = (gidx == NCHAIN - 1);
#pragma unroll
            for (int mi = 0; mi < 4; ++mi)
#pragma unroll
                for (int h2 = 0; h2 < 2; ++h2) {
                    int row = rbase + mi * 16 + h2 * 8 + gid;
#pragma unroll
                    for (int ni = 0; ni < 4; ++ni) {
                        int col = cbase + ni * 8 + tig * 2;
                        size_t uoff  = (size_t)row * HID + col;
                        size_t ysoff = (size_t)row * (2 * HID) + col * 2;
                        float a0 = acc[mi][ni][h2 * 2 + 0];
                        float a1 = acc[mi][ni][h2 * 2 + 1];
                        float4 ys = __ldcg(reinterpret_cast<const float4*>(yS + ysoff));
                        ys.x += dt * a0;
                        ys.y += dt * a1;
                        float2 qe = __half22float2(
                            *reinterpret_cast<const __half2*>(qh + uoff));
                        float u0 = tanh_ap(ys.x + tcoef * qe.x + b1t[col]);
                        float u1 = tanh_ap(ys.y + tcoef * qe.y + b1t[col + 1]);
                        ys.z += u0;
                        ys.w += u1;
                        *reinterpret_cast<__half2*>(Cu + uoff) =
                            __floats2half2_rn(u0, u1);
                        *reinterpret_cast<float4*>(yS + ysoff) = ys;
                        if (last)
                            *reinterpret_cast<__half2*>(Sh + uoff) =
                                __floats2half2_rn(ys.z, ys.w);
                    }
                }
        } else if (kind == 3) {
#pragma unroll
            for (int mi = 0; mi < 4; ++mi)
#pragma unroll
                for (int h2 = 0; h2 < 2; ++h2) {
                    int row = rbase + mi * 16 + h2 * 8 + gid;
#pragma unroll
                    for (int ni = 0; ni < 4; ++ni) {
                        int col = cbase + ni * 8 + tig * 2;
                        size_t off = (size_t)row * HID + col;
                        *reinterpret_cast<float2*>(o1 + off) = make_float2(
                            acc[mi][ni][h2 * 2 + 0], acc[mi][ni][h2 * 2 + 1]);
                    }
                }
        } else {
#pragma unroll
            for (int mi = 0; mi < 4; ++mi)
#pragma unroll
                for (int h2 = 0; h2 < 2; ++h2) {
                    int row = rbase + mi * 16 + h2 * 8 + gid;
#pragma unroll
                    for (int ni = 0; ni < 4; ++ni) {
                        int col = cbase + ni * 8 + tig * 2;
                        size_t off = (size_t)row * HID + col;
                        float2 ov = __ldcg(reinterpret_cast<const float2*>(o1 + off));
                        *reinterpret_cast<float2*>(out + off) = make_float2(
                            ov.x + dt * acc[mi][ni][h2 * 2 + 0] + b2ro[col],
                            ov.y + dt * acc[mi][ni][h2 * 2 + 1] + b2ro[col + 1]);
                    }
                }
        }

        if (kind != 4) {
            __threadfence();
            __syncthreads();
            if (tid == 0) {
                int ci;
                if (kind == 0)      ci = 0;
                else if (kind == 1) ci = 1;
                else if (kind == 2) ci = 2 + gidx;
                else                ci = 51;
                atomicAdd(&g_done[ci][bm], 1u);
            }
        }
    }
}

// ---------------------------------------------------------------------------
// prep1: all transposes + fp16 conversions + counter reset, one launch
// ---------------------------------------------------------------------------
__device__ __forceinline__ void transpose_block(
    const float* __restrict__ in, __half* __restrict__ out,
    int K, int N, int bx, int by, int tid)
{
    __shared__ float t[32][33];
    const int k0 = by * 32, n0 = bx * 32;
    const int x = tid & 31, y = tid >> 5;   // y in 0..7
#pragma unroll
    for (int i = 0; i < 32; i += 8)
        t[y + i][x] = in[(size_t)(k0 + y + i) * N + n0 + x];
    __syncthreads();
#pragma unroll
    for (int i = 0; i < 32; i += 8)
        out[(size_t)(n0 + y + i) * K + k0 + x] = __float2half_rn(t[x][y + i]);
}

__global__ void prep1(const float* __restrict__ x0,
                      const float* __restrict__ W_pe, const float* __restrict__ W_hi,
                      const float* __restrict__ W1,  const float* __restrict__ W_ro,
                      const float* __restrict__ W2,
                      __half* __restrict__ wpe, __half* __restrict__ whi,
                      __half* __restrict__ w1a, __half* __restrict__ w1b,
                      __half* __restrict__ wro,
                      __half* __restrict__ x0h, __half* __restrict__ w2h)
{
    const int b = blockIdx.x, tid = threadIdx.x;
    if (b < 256) {
        transpose_block(W_pe, wpe, DIN, PATHD, b & 7, b >> 3, tid);
    } else if (b < 1280) {
        int v = b - 256;  transpose_block(W_hi, whi, DIN, HID, v & 31, v >> 5, tid);
    } else if (b < 2304) {
        int v = b - 1280; transpose_block(W1, w1a, HID, HID, v & 31, v >> 5, tid);
    } else if (b < 2560) {
        int v = b - 2304; transpose_block(W1 + (size_t)HID * HID, w1b,
                                          PATHD, HID, v & 31, v >> 5, tid);
    } else if (b < 3584) {
        int v = b - 2560; transpose_block(W_ro, wro, HID, HID, v & 31, v >> 5, tid);
    } else if (b < 11776) {
        int i = (b - 3584) * 256 + tid;           // x0: n4 = 2097152
        float4 v = reinterpret_cast<const float4*>(x0)[i];
        __half2* o = reinterpret_cast<__half2*>(x0h);
        o[i * 2 + 0] = __floats2half2_rn(v.x, v.y);
        o[i * 2 + 1] = __floats2half2_rn(v.z, v.w);
    } else if (b < 12800) {
        int i = (b - 11776) * 256 + tid;          // W2: w4 = 262144
        float4 v = reinterpret_cast<const float4*>(W2)[i];
        __half2* o = reinterpret_cast<__half2*>(w2h);
        o[i * 2 + 0] = __floats2half2_rn(v.x, v.y);
        o[i * 2 + 1] = __floats2half2_rn(v.z, v.w);
    } else {
        int i = (b - 12800) * 256 + tid;
        int n = NCTR * ROWB;
        unsigned int* p = &g_done[0][0];
        if (i < n) p[i] = 0;
        if (i == n) g_tile_ctr = 0;
    }
}

// ---------------------------------------------------------------------------
// prep2: cv = b2@W1a (+ b1t), b2ro = b2@Wro + b_ro
// ---------------------------------------------------------------------------
__global__ void prep2(const __half* __restrict__ w1a, const __half* __restrict__ wro,
                      const float* __restrict__ b1, const float* __restrict__ b2,
                      const float* __restrict__ b_ro,
                      float* __restrict__ cv, float* __restrict__ b1t,
                      float* __restrict__ b2ro, float dt)
{
    __shared__ float red[256];
    const int b = blockIdx.x;
    const bool first = (b < HID);
    const int n = first ? b : (b - HID);
    const __half* Wt = first ? w1a : wro;
    float s = 0.f;
    for (int j = threadIdx.x; j < HID; j += 256)
        s += b2[j] * __half2float(Wt[(size_t)n * HID + j]);
    red[threadIdx.x] = s;
    __syncthreads();
    for (int k = 128; k > 0; k >>= 1) {
        if (threadIdx.x < k) red[threadIdx.x] += red[threadIdx.x + k];
        __syncthreads();
    }
    if (threadIdx.x == 0) {
        if (first) { cv[n] = red[0]; b1t[n] = b1[n] - dt * red[0]; }
        else       { b2ro[n] = red[0] + b_ro[n]; }
    }
}

extern "C" void kernel_launch(void* const* d_in, const int* in_sizes, int n_in,
                              void* d_out, int out_size)
{
    const float* x0   = (const float*)d_in[0];
    const float* W_pe = (const float*)d_in[1];
    const float* b_pe = (const float*)d_in[2];
    const float* W_hi = (const float*)d_in[3];
    const float* b_hi = (const float*)d_in[4];
    const float* W1   = (const float*)d_in[5];
    const float* b1   = (const float*)d_in[6];
    const float* W2   = (const float*)d_in[7];
    const float* b2   = (const float*)d_in[8];
    const float* W_ro = (const float*)d_in[9];
    const float* b_ro = (const float*)d_in[10];
    float* out = (float*)d_out;

    __half *x0h, *gh, *qh, *z0h, *u0s, *u1s, *Shp;
    __half *wpe, *whi, *w1a, *w1b, *wro, *w2h, *w21, *w2ro;
    float *yS, *o1, *cv, *b1t, *b2ro;
    cudaGetSymbolAddress((void**)&x0h, x0h_buf);
    cudaGetSymbolAddress((void**)&gh,  gh_buf);
    cudaGetSymbolAddress((void**)&qh,  qh_buf);
    cudaGetSymbolAddress((void**)&z0h, z0h_buf);
    cudaGetSymbolAddress((void**)&u0s, u0_buf);
    cudaGetSymbolAddress((void**)&u1s, u1_buf);
    cudaGetSymbolAddress((void**)&Shp, Sh_buf);
    cudaGetSymbolAddress((void**)&yS,  yS_buf);
    cudaGetSymbolAddress((void**)&o1,  o1_buf);
    cudaGetSymbolAddress((void**)&wpe, WpeT);
    cudaGetSymbolAddress((void**)&whi, WhiT);
    cudaGetSymbolAddress((void**)&w1a, W1aT);
    cudaGetSymbolAddress((void**)&w1b, W1bT);
    cudaGetSymbolAddress((void**)&wro, WroT);
    cudaGetSymbolAddress((void**)&w2h, W2h);
    cudaGetSymbolAddress((void**)&w21, W21T_b);
    cudaGetSymbolAddress((void**)&w2ro, W2roT_b);
    cudaGetSymbolAddress((void**)&cv,  cvec_b);
    cudaGetSymbolAddress((void**)&b1t, b1t_b);
    cudaGetSymbolAddress((void**)&b2ro, b2ro_b);

    const float dt = 1.0f / (float)NSTEP;

    // prep1: transposes + conversions + counter reset (one launch)
    prep1<<<12814, 256>>>(x0, W_pe, W_hi, W1, W_ro, W2,
                          wpe, whi, w1a, w1b, wro, x0h, w2h);

    // prep2: cv/b1t/b2ro (one launch)
    prep2<<<2 * HID, 256>>>(w1a, wro, b1, b2, b_ro, cv, b1t, b2ro, dt);

    // launch A: all independent GEMMs in one grid
    cudaFuncSetAttribute(gemm_indep,
                         cudaFuncAttributeMaxDynamicSharedMemorySize, SMEM_BYTES);
    gemm_indep<<<768, NTHREADS, SMEM_BYTES>>>(
        x0h, wpe, whi, w1a, wro, w2h, w21, w2ro, gh, z0h, b_pe, b_hi);

    // persistent: q -> y0 -> chain -> o1 -> final
    int dev = 0, nsm = 148;
    cudaGetDevice(&dev);
    cudaDeviceGetAttribute(&nsm, cudaDevAttrMultiProcessorCount, dev);
    cudaFuncSetAttribute(cde_chain,
                         cudaFuncAttributeMaxDynamicSharedMemorySize, SMEM_BYTES);
    cde_chain<<<2 * nsm, NTHREADS, SMEM_BYTES>>>(
        gh, w1b, w1a, w21, wro, w2ro, z0h, u0s, u1s, Shp, qh,
        yS, o1, out, cv, b1t, b2ro, dt);
}

// round 16
// speedup vs baseline: 1.0952x; 1.0862x over previous
#include <cuda_runtime.h>
#include <cuda_fp16.h>
#include <cstdint>

// ---------------------------------------------------------------------------
// NeuralCDE rollout — R15 structure with BK=64 (halved sync epochs).
//   prep1 (1 launch): all transposes, fp16 converts, counter reset
//   prep2 (1 launch): cv=b2@W1a (+b1t), b2ro=b2@Wro+b_ro
//   launch A (768 indep tiles): W21, W2ro, g, z0h
//   persistent: q2 -> y0 -> 49x chain -> o1 (filler) -> final
//   u ping-pong slabs; y/S interleaved float4 stream.
// ---------------------------------------------------------------------------

static constexpr int BATCH = 8192;
static constexpr int DIN   = 1024;
static constexpr int PATHD = 256;
static constexpr int HID   = 1024;
static constexpr int NSTEP = 50;
static constexpr int NCHAIN = NSTEP - 1;               // 49
static constexpr int TPG   = (BATCH/128) * (HID/128);  // 512
static constexpr int ROWB  = BATCH / 128;              // 64

// persistent slot layout
static constexpr int S_Q   = 0;                        // 512
static constexpr int S_Y0  = S_Q + TPG;                // 512
static constexpr int S_CH  = S_Y0 + TPG;               // 49*512
static constexpr int S_O1  = S_CH + NCHAIN * TPG;      // 512
static constexpr int S_FIN = S_O1 + TPG;               // 512
static constexpr int S_END = S_FIN + TPG;
// counters: 0=q, 1=y0, 2..50=chain 0..48, 51=o1
static constexpr int NCTR  = 52;

// ---------------- device scratch ----------------
__device__ __half x0h_buf[(size_t)BATCH * DIN];
__device__ __half gh_buf [(size_t)BATCH * PATHD];
__device__ __half qh_buf [(size_t)BATCH * HID];
__device__ __half z0h_buf[(size_t)BATCH * HID];
__device__ __half u0_buf [(size_t)BATCH * HID];
__device__ __half u1_buf [(size_t)BATCH * HID];
__device__ __half Sh_buf [(size_t)BATCH * HID];
__device__ float  yS_buf [(size_t)BATCH * HID * 2];   // (y0,y1,S0,S1) per 2 cols
__device__ float  o1_buf [(size_t)BATCH * HID];
__device__ __half WpeT  [(size_t)PATHD * DIN];
__device__ __half WhiT  [(size_t)HID * DIN];
__device__ __half W1aT  [(size_t)HID * HID];
__device__ __half W1bT  [(size_t)HID * PATHD];
__device__ __half WroT  [(size_t)HID * HID];
__device__ __half W2h   [(size_t)HID * HID];
__device__ __half W21T_b[(size_t)HID * HID];
__device__ __half W2roT_b[(size_t)HID * HID];
__device__ float  cvec_b[HID];
__device__ float  b1t_b [HID];
__device__ float  b2ro_b[HID];

__device__ unsigned int g_done[NCTR][ROWB];
__device__ unsigned int g_tile_ctr;

// ---------------- tile configuration ----------------
static constexpr int BM = 128, BN = 128, BK = 64;
static constexpr int STAGES = 3, NTHREADS = 256;
static constexpr int STR  = BK + 8;                    // 72 halves (144 B)
static constexpr int ASZ  = BM * STR;                  // 9216
static constexpr int BSZ  = BN * STR;                  // 9216
static constexpr int SMEM_BYTES = STAGES * (ASZ + BSZ) * 2;  // 110592 B

__device__ __forceinline__ void ldmx4(uint32_t& r0, uint32_t& r1,
                                      uint32_t& r2, uint32_t& r3, uint32_t a) {
    asm volatile("ldmatrix.sync.aligned.m8n8.x4.shared.b16 {%0,%1,%2,%3}, [%4];"
                 : "=r"(r0), "=r"(r1), "=r"(r2), "=r"(r3) : "r"(a));
}
__device__ __forceinline__ float tanh_ap(float x) {
    float y;
    asm("tanh.approx.f32 %0, %1;" : "=f"(y) : "f"(x));
    return y;
}
__device__ __forceinline__ void spin_ge(volatile unsigned int* c, unsigned int v) {
    while (*c < v) __nanosleep(64);
}

// acc = A[bm*128.., :K] @ B[bn*128.., :K]^T
__device__ __forceinline__ void mainloop_f16(
    const __half* __restrict__ A, const __half* __restrict__ Bw,
    int K, int bm, int bn, __half* As, __half* Bs,
    float (&acc)[4][4][4])
{
    const int tid  = threadIdx.x;
    const int wid  = tid >> 5, lane = tid & 31;
    const int warp_m = wid & 1, warp_n = wid >> 1;
    const int KT = K / BK;

#pragma unroll
    for (int a = 0; a < 4; ++a)
#pragma unroll
        for (int b = 0; b < 4; ++b)
#pragma unroll
            for (int c = 0; c < 4; ++c) acc[a][b][c] = 0.f;

    auto load_tile = [&](int kt, int stage) {
        const __half* Ag = A + (size_t)(bm * BM) * K + (size_t)kt * BK;
        __half* Asb = As + stage * ASZ;
#pragma unroll
        for (int i = 0; i < 4; ++i) {
            int lin = i * NTHREADS + tid;
            int r = lin >> 3, c = (lin & 7) << 3;
            uint32_t sa = (uint32_t)__cvta_generic_to_shared(Asb + r * STR + c);
            asm volatile("cp.async.cg.shared.global [%0], [%1], 16;"
                         :: "r"(sa), "l"(Ag + (size_t)r * K + c));
        }
        const __half* Bg = Bw + (size_t)(bn * BN) * K + (size_t)kt * BK;
        __half* Bsb = Bs + stage * BSZ;
#pragma unroll
        for (int i = 0; i < 4; ++i) {
            int lin = i * NTHREADS + tid;
            int r = lin >> 3, c = (lin & 7) << 3;
            uint32_t sa = (uint32_t)__cvta_generic_to_shared(Bsb + r * STR + c);
            asm volatile("cp.async.cg.shared.global [%0], [%1], 16;"
                         :: "r"(sa), "l"(Bg + (size_t)r * K + c));
        }
        asm volatile("cp.async.commit_group;");
    };

    const int a_row  = warp_m * 64 + (lane & 15);
    const int a_koff = (lane >> 4) << 3;
    const int b_row  = warp_n * 32 + (lane & 7) + ((lane >> 4) << 3);
    const int b_koff = ((lane >> 3) & 1) << 3;

    for (int s = 0; s < STAGES - 1 && s < KT; ++s) load_tile(s, s);

    for (int kt = 0; kt < KT; ++kt) {
        if (kt < KT - (STAGES - 1))
            asm volatile("cp.async.wait_group %0;" :: "n"(STAGES - 2));
        else
            asm volatile("cp.async.wait_group 0;");
        __syncthreads();

        int pf = kt + STAGES - 1;
        if (pf < KT) load_tile(pf, pf % STAGES);

        const __half* Asb = As + (kt % STAGES) * ASZ;
        const __half* Bsb = Bs + (kt % STAGES) * BSZ;
        const uint32_t a_base = (uint32_t)__cvta_generic_to_shared(
            Asb + (size_t)a_row * STR + a_koff);
        const uint32_t b_base = (uint32_t)__cvta_generic_to_shared(
            Bsb + (size_t)b_row * STR + b_koff);

#pragma unroll
        for (int ks = 0; ks < BK / 16; ++ks) {
            uint32_t af[4][4], bf[4][2];
#pragma unroll
            for (int mi = 0; mi < 4; ++mi)
                ldmx4(af[mi][0], af[mi][1], af[mi][2], af[mi][3],
                      a_base + (mi * 16 * STR + ks * 16) * 2);
#pragma unroll
            for (int np = 0; np < 2; ++np)
                ldmx4(bf[np*2][0], bf[np*2][1], bf[np*2+1][0], bf[np*2+1][1],
                      b_base + (np * 16 * STR + ks * 16) * 2);
#pragma unroll
            for (int mi = 0; mi < 4; ++mi)
#pragma unroll
                for (int ni = 0; ni < 4; ++ni) {
                    asm volatile(
                        "mma.sync.aligned.m16n8k16.row.col.f32.f16.f16.f32 "
                        "{%0,%1,%2,%3}, {%4,%5,%6,%7}, {%8,%9}, {%0,%1,%2,%3};"
                        : "+f"(acc[mi][ni][0]), "+f"(acc[mi][ni][1]),
                          "+f"(acc[mi][ni][2]), "+f"(acc[mi][ni][3])
                        : "r"(af[mi][0]), "r"(af[mi][1]), "r"(af[mi][2]), "r"(af[mi][3]),
                          "r"(bf[ni][0]), "r"(bf[ni][1]));
                }
        }
    }
}

// ---------------------------------------------------------------------------
// launch A: merged independent prologue GEMMs (768 one-tile blocks)
// ---------------------------------------------------------------------------
__global__ __launch_bounds__(NTHREADS, 2)
void gemm_indep(const __half* __restrict__ x0h,
                const __half* __restrict__ wpe, const __half* __restrict__ whi,
                const __half* __restrict__ w1a, const __half* __restrict__ wro,
                const __half* __restrict__ w2h,
                __half* __restrict__ w21, __half* __restrict__ w2ro,
                __half* __restrict__ gh, __half* __restrict__ z0h,
                const float* __restrict__ b_pe, const float* __restrict__ b_hi)
{
    extern __shared__ __half smem[];
    __half* As = smem;
    __half* Bs = smem + STAGES * ASZ;

    const int v = blockIdx.x;
    const __half* A;
    const __half* Bw;
    __half* C;
    const float* bias = nullptr;
    int K = HID, N = HID, bm, bn;

    if (v < 64)        { A = w1a; Bw = w2h; C = w21;  bm = v >> 3; bn = v & 7; }
    else if (v < 128)  { A = wro; Bw = w2h; C = w2ro; int t = v - 64; bm = t >> 3; bn = t & 7; }
    else if (v < 256)  { A = x0h; Bw = wpe; C = gh; bias = b_pe; K = DIN; N = PATHD;
                         int t = v - 128; bm = t >> 1; bn = t & 1; }
    else               { A = x0h; Bw = whi; C = z0h; bias = b_hi; K = DIN;
                         int t = v - 256; bm = t >> 3; bn = t & 7; }

    float acc[4][4][4];
    mainloop_f16(A, Bw, K, bm, bn, As, Bs, acc);

    const int tid = threadIdx.x, wid = tid >> 5, lane = tid & 31;
    const int gid = lane >> 2, tig = lane & 3;
    const int rbase = bm * BM + (wid & 1) * 64;
    const int cbase = bn * BN + (wid >> 1) * 32;
#pragma unroll
    for (int mi = 0; mi < 4; ++mi)
#pragma unroll
        for (int h2 = 0; h2 < 2; ++h2) {
            int row = rbase + mi * 16 + h2 * 8 + gid;
#pragma unroll
            for (int ni = 0; ni < 4; ++ni) {
                int col = cbase + ni * 8 + tig * 2;
                size_t off = (size_t)row * N + col;
                float v0 = acc[mi][ni][h2 * 2 + 0];
                float v1 = acc[mi][ni][h2 * 2 + 1];
                if (bias) { v0 += bias[col]; v1 += bias[col + 1]; }
                *reinterpret_cast<__half2*>(C + off) = __floats2half2_rn(v0, v1);
            }
        }
}

// ---------------------------------------------------------------------------
// persistent kernel: q -> y0 -> 49 chain -> o1 -> final
// ---------------------------------------------------------------------------
__global__ __launch_bounds__(NTHREADS, 2)
void cde_chain(const __half* __restrict__ gh, const __half* __restrict__ w1b,
               const __half* __restrict__ w1a,
               const __half* __restrict__ W21, const __half* __restrict__ wro,
               const __half* __restrict__ w2ro,
               const __half* __restrict__ z0h,
               __half* __restrict__ u0s, __half* __restrict__ u1s,
               __half* __restrict__ Sh, __half* __restrict__ qh,
               float* __restrict__ yS,
               float* __restrict__ o1, float* __restrict__ out,
               const float* __restrict__ cv,
               const float* __restrict__ b1t, const float* __restrict__ b2ro,
               float dt)
{
    extern __shared__ __half smem[];
    __half* As = smem;
    __half* Bs = smem + STAGES * ASZ;
    __shared__ unsigned int s_tile;

    const int tid = threadIdx.x, wid = tid >> 5, lane = tid & 31;
    const int gid = lane >> 2, tig = lane & 3;

    while (true) {
        if (tid == 0) s_tile = atomicAdd(&g_tile_ctr, 1u);
        __syncthreads();
        unsigned int v = s_tile;
        if (v >= (unsigned)S_END) break;

        // kind: 0=q 1=y0 2=chain 3=o1 4=final
        int kind, gidx = 0, t;
        if (v < (unsigned)S_Y0)       { kind = 0; t = v; }
        else if (v < (unsigned)S_CH)  { kind = 1; t = v - S_Y0; }
        else if (v < (unsigned)S_O1)  { kind = 2; gidx = (v - S_CH) >> 9; t = (v - S_CH) & 511; }
        else if (v < (unsigned)S_FIN) { kind = 3; t = v - S_O1; }
        else                          { kind = 4; t = v - S_FIN; }
        const int bm = t >> 3, bn = t & 7;

        // dependencies (row-block granularity; strictly earlier slots only)
        if (tid == 0) {
            if (kind == 1) {
                spin_ge(&g_done[0][bm], 8u);
                __threadfence();
            } else if (kind == 2) {
                spin_ge(&g_done[1 + gidx][bm], 8u);
                __threadfence();
            } else if (kind == 4) {
                spin_ge(&g_done[1 + NCHAIN][bm], 8u);
                spin_ge(&g_done[51][bm], 8u);
                __threadfence();
            }
        }
        __syncthreads();

        const __half* A;
        const __half* Bw;
        int K = HID;
        if (kind == 0)      { A = gh;  Bw = w1b; K = PATHD; }
        else if (kind == 1) { A = z0h; Bw = w1a; }
        else if (kind == 2) { A = ((gidx + 1) & 1) ? u1s : u0s; Bw = W21; }
        else if (kind == 3) { A = z0h; Bw = wro; }
        else                { A = Sh;  Bw = w2ro; }

        float acc[4][4][4];
        mainloop_f16(A, Bw, K, bm, bn, As, Bs, acc);

        const int rbase = bm * BM + (wid & 1) * 64;
        const int cbase = bn * BN + (wid >> 1) * 32;

        if (kind == 0) {
#pragma unroll
            for (int mi = 0; mi < 4; ++mi)
#pragma unroll
                for (int h2 = 0; h2 < 2; ++h2) {
                    int row = rbase + mi * 16 + h2 * 8 + gid;
#pragma unroll
                    for (int ni = 0; ni < 4; ++ni) {
                        int col = cbase + ni * 8 + tig * 2;
                        size_t off = (size_t)row * HID + col;
                        *reinterpret_cast<__half2*>(qh + off) = __floats2half2_rn(
                            acc[mi][ni][h2 * 2 + 0] + cv[col],
                            acc[mi][ni][h2 * 2 + 1] + cv[col + 1]);
                    }
                }
        } else if (kind == 1) {
#pragma unroll
            for (int mi = 0; mi < 4; ++mi)
#pragma unroll
                for (int h2 = 0; h2 < 2; ++h2) {
                    int row = rbase + mi * 16 + h2 * 8 + gid;
#pragma unroll
                    for (int ni = 0; ni < 4; ++ni) {
                        int col = cbase + ni * 8 + tig * 2;
                        size_t uoff  = (size_t)row * HID + col;
                        size_t ysoff = (size_t)row * (2 * HID) + col * 2;
                        float a0 = acc[mi][ni][h2 * 2 + 0];
                        float a1 = acc[mi][ni][h2 * 2 + 1];
                        float2 qe = __half22float2(
                            *reinterpret_cast<const __half2*>(qh + uoff));
                        float u0 = tanh_ap(a0 + dt * qe.x + b1t[col]);
                        float u1 = tanh_ap(a1 + dt * qe.y + b1t[col + 1]);
                        *reinterpret_cast<__half2*>(u1s + uoff) =
                            __floats2half2_rn(u0, u1);
                        *reinterpret_cast<float4*>(yS + ysoff) =
                            make_float4(a0, a1, u0, u1);
                    }
                }
        } else if (kind == 2) {
            __half* Cu = (gidx & 1) ? u1s : u0s;
            const float tcoef = dt * (float)(gidx + 2);
            const bool last = (gidx == NCHAIN - 1);
#pragma unroll
            for (int mi = 0; mi < 4; ++mi)
#pragma unroll
                for (int h2 = 0; h2 < 2; ++h2) {
                    int row = rbase + mi * 16 + h2 * 8 + gid;
#pragma unroll
                    for (int ni = 0; ni < 4; ++ni) {
                        int col = cbase + ni * 8 + tig * 2;
                        size_t uoff  = (size_t)row * HID + col;
                        size_t ysoff = (size_t)row * (2 * HID) + col * 2;
                        float a0 = acc[mi][ni][h2 * 2 + 0];
                        float a1 = acc[mi][ni][h2 * 2 + 1];
                        float4 ys = __ldcg(reinterpret_cast<const float4*>(yS + ysoff));
                        ys.x += dt * a0;
                        ys.y += dt * a1;
                        float2 qe = __half22float2(
                            *reinterpret_cast<const __half2*>(qh + uoff));
                        float u0 = tanh_ap(ys.x + tcoef * qe.x + b1t[col]);
                        float u1 = tanh_ap(ys.y + tcoef * qe.y + b1t[col + 1]);
                        ys.z += u0;
                        ys.w += u1;
                        *reinterpret_cast<__half2*>(Cu + uoff) =
                            __floats2half2_rn(u0, u1);
                        *reinterpret_cast<float4*>(yS + ysoff) = ys;
                        if (last)
                            *reinterpret_cast<__half2*>(Sh + uoff) =
                                __floats2half2_rn(ys.z, ys.w);
                    }
                }
        } else if (kind == 3) {
#pragma unroll
            for (int mi = 0; mi < 4; ++mi)
#pragma unroll
                for (int h2 = 0; h2 < 2; ++h2) {
                    int row = rbase + mi * 16 + h2 * 8 + gid;
#pragma unroll
                    for (int ni = 0; ni < 4; ++ni) {
                        int col = cbase + ni * 8 + tig * 2;
                        size_t off = (size_t)row * HID + col;
                        *reinterpret_cast<float2*>(o1 + off) = make_float2(
                            acc[mi][ni][h2 * 2 + 0], acc[mi][ni][h2 * 2 + 1]);
                    }
                }
        } else {
#pragma unroll
            for (int mi = 0; mi < 4; ++mi)
#pragma unroll
                for (int h2 = 0; h2 < 2; ++h2) {
                    int row = rbase + mi * 16 + h2 * 8 + gid;
#pragma unroll
                    for (int ni = 0; ni < 4; ++ni) {
                        int col = cbase + ni * 8 + tig * 2;
                        size_t off = (size_t)row * HID + col;
                        float2 ov = __ldcg(reinterpret_cast<const float2*>(o1 + off));
                        *reinterpret_cast<float2*>(out + off) = make_float2(
                            ov.x + dt * acc[mi][ni][h2 * 2 + 0] + b2ro[col],
                            ov.y + dt * acc[mi][ni][h2 * 2 + 1] + b2ro[col + 1]);
                    }
                }
        }

        if (kind != 4) {
            __threadfence();
            __syncthreads();
            if (tid == 0) {
                int ci;
                if (kind == 0)      ci = 0;
                else if (kind == 1) ci = 1;
                else if (kind == 2) ci = 2 + gidx;
                else                ci = 51;
                atomicAdd(&g_done[ci][bm], 1u);
            }
        }
    }
}

// ---------------------------------------------------------------------------
// prep1: all transposes + fp16 conversions + counter reset, one launch
// ---------------------------------------------------------------------------
__device__ __forceinline__ void transpose_block(
    const float* __restrict__ in, __half* __restrict__ out,
    int K, int N, int bx, int by, int tid)
{
    __shared__ float t[32][33];
    const int k0 = by * 32, n0 = bx * 32;
    const int x = tid & 31, y = tid >> 5;   // y in 0..7
#pragma unroll
    for (int i = 0; i < 32; i += 8)
        t[y + i][x] = in[(size_t)(k0 + y + i) * N + n0 + x];
    __syncthreads();
#pragma unroll
    for (int i = 0; i < 32; i += 8)
        out[(size_t)(n0 + y + i) * K + k0 + x] = __float2half_rn(t[x][y + i]);
}

__global__ void prep1(const float* __restrict__ x0,
                      const float* __restrict__ W_pe, const float* __restrict__ W_hi,
                      const float* __restrict__ W1,  const float* __restrict__ W_ro,
                      const float* __restrict__ W2,
                      __half* __restrict__ wpe, __half* __restrict__ whi,
                      __half* __restrict__ w1a, __half* __restrict__ w1b,
                      __half* __restrict__ wro,
                      __half* __restrict__ x0h, __half* __restrict__ w2h)
{
    const int b = blockIdx.x, tid = threadIdx.x;
    if (b < 256) {
        transpose_block(W_pe, wpe, DIN, PATHD, b & 7, b >> 3, tid);
    } else if (b < 1280) {
        int v = b - 256;  transpose_block(W_hi, whi, DIN, HID, v & 31, v >> 5, tid);
    } else if (b < 2304) {
        int v = b - 1280; transpose_block(W1, w1a, HID, HID, v & 31, v >> 5, tid);
    } else if (b < 2560) {
        int v = b - 2304; transpose_block(W1 + (size_t)HID * HID, w1b,
                                          PATHD, HID, v & 31, v >> 5, tid);
    } else if (b < 3584) {
        int v = b - 2560; transpose_block(W_ro, wro, HID, HID, v & 31, v >> 5, tid);
    } else if (b < 11776) {
        int i = (b - 3584) * 256 + tid;           // x0: n4 = 2097152
        float4 v = reinterpret_cast<const float4*>(x0)[i];
        __half2* o = reinterpret_cast<__half2*>(x0h);
        o[i * 2 + 0] = __floats2half2_rn(v.x, v.y);
        o[i * 2 + 1] = __floats2half2_rn(v.z, v.w);
    } else if (b < 12800) {
        int i = (b - 11776) * 256 + tid;          // W2: w4 = 262144
        float4 v = reinterpret_cast<const float4*>(W2)[i];
        __half2* o = reinterpret_cast<__half2*>(w2h);
        o[i * 2 + 0] = __floats2half2_rn(v.x, v.y);
        o[i * 2 + 1] = __floats2half2_rn(v.z, v.w);
    } else {
        int i = (b - 12800) * 256 + tid;
        int n = NCTR * ROWB;
        unsigned int* p = &g_done[0][0];
        if (i < n) p[i] = 0;
        if (i == n) g_tile_ctr = 0;
    }
}

// ---------------------------------------------------------------------------
// prep2: cv = b2@W1a (+ b1t), b2ro = b2@Wro + b_ro
// ---------------------------------------------------------------------------
__global__ void prep2(const __half* __restrict__ w1a, const __half* __restrict__ wro,
                      const float* __restrict__ b1, const float* __restrict__ b2,
                      const float* __restrict__ b_ro,
                      float* __restrict__ cv, float* __restrict__ b1t,
                      float* __restrict__ b2ro, float dt)
{
    __shared__ float red[256];
    const int b = blockIdx.x;
    const bool first = (b < HID);
    const int n = first ? b : (b - HID);
    const __half* Wt = first ? w1a : wro;
    float s = 0.f;
    for (int j = threadIdx.x; j < HID; j += 256)
        s += b2[j] * __half2float(Wt[(size_t)n * HID + j]);
    red[threadIdx.x] = s;
    __syncthreads();
    for (int k = 128; k > 0; k >>= 1) {
        if (threadIdx.x < k) red[threadIdx.x] += red[threadIdx.x + k];
        __syncthreads();
    }
    if (threadIdx.x == 0) {
        if (first) { cv[n] = red[0]; b1t[n] = b1[n] - dt * red[0]; }
        else       { b2ro[n] = red[0] + b_ro[n]; }
    }
}

extern "C" void kernel_launch(void* const* d_in, const int* in_sizes, int n_in,
                              void* d_out, int out_size)
{
    const float* x0   = (const float*)d_in[0];
    const float* W_pe = (const float*)d_in[1];
    const float* b_pe = (const float*)d_in[2];
    const float* W_hi = (const float*)d_in[3];
    const float* b_hi = (const float*)d_in[4];
    const float* W1   = (const float*)d_in[5];
    const float* b1   = (const float*)d_in[6];
    const float* W2   = (const float*)d_in[7];
    const float* b2   = (const float*)d_in[8];
    const float* W_ro = (const float*)d_in[9];
    const float* b_ro = (const float*)d_in[10];
    float* out = (float*)d_out;

    __half *x0h, *gh, *qh, *z0h, *u0s, *u1s, *Shp;
    __half *wpe, *whi, *w1a, *w1b, *wro, *w2h, *w21, *w2ro;
    float *yS, *o1, *cv, *b1t, *b2ro;
    cudaGetSymbolAddress((void**)&x0h, x0h_buf);
    cudaGetSymbolAddress((void**)&gh,  gh_buf);
    cudaGetSymbolAddress((void**)&qh,  qh_buf);
    cudaGetSymbolAddress((void**)&z0h, z0h_buf);
    cudaGetSymbolAddress((void**)&u0s, u0_buf);
    cudaGetSymbolAddress((void**)&u1s, u1_buf);
    cudaGetSymbolAddress((void**)&Shp, Sh_buf);
    cudaGetSymbolAddress((void**)&yS,  yS_buf);
    cudaGetSymbolAddress((void**)&o1,  o1_buf);
    cudaGetSymbolAddress((void**)&wpe, WpeT);
    cudaGetSymbolAddress((void**)&whi, WhiT);
    cudaGetSymbolAddress((void**)&w1a, W1aT);
    cudaGetSymbolAddress((void**)&w1b, W1bT);
    cudaGetSymbolAddress((void**)&wro, WroT);
    cudaGetSymbolAddress((void**)&w2h, W2h);
    cudaGetSymbolAddress((void**)&w21, W21T_b);
    cudaGetSymbolAddress((void**)&w2ro, W2roT_b);
    cudaGetSymbolAddress((void**)&cv,  cvec_b);
    cudaGetSymbolAddress((void**)&b1t, b1t_b);
    cudaGetSymbolAddress((void**)&b2ro, b2ro_b);

    const float dt = 1.0f / (float)NSTEP;

    // prep1: transposes + conversions + counter reset (one launch)
    prep1<<<12814, 256>>>(x0, W_pe, W_hi, W1, W_ro, W2,
                          wpe, whi, w1a, w1b, wro, x0h, w2h);

    // prep2: cv/b1t/b2ro (one launch)
    prep2<<<2 * HID, 256>>>(w1a, wro, b1, b2, b_ro, cv, b1t, b2ro, dt);

    // launch A: all independent GEMMs in one grid
    cudaFuncSetAttribute(gemm_indep,
                         cudaFuncAttributeMaxDynamicSharedMemorySize, SMEM_BYTES);
    gemm_indep<<<768, NTHREADS, SMEM_BYTES>>>(
        x0h, wpe, whi, w1a, wro, w2h, w21, w2ro, gh, z0h, b_pe, b_hi);

    // persistent: q -> y0 -> chain -> o1 -> final
    int dev = 0, nsm = 148;
    cudaGetDevice(&dev);
    cudaDeviceGetAttribute(&nsm, cudaDevAttrMultiProcessorCount, dev);
    cudaFuncSetAttribute(cde_chain,
                         cudaFuncAttributeMaxDynamicSharedMemorySize, SMEM_BYTES);
    cde_chain<<<2 * nsm, NTHREADS, SMEM_BYTES>>>(
        gh, w1b, w1a, w21, wro, w2ro, z0h, u0s, u1s, Shp, qh,
        yS, o1, out, cv, b1t, b2ro, dt);
}